// round 1
// baseline (speedup 1.0000x reference)
#include <cuda_runtime.h>
#include <cstdint>

// Problem constants
#define NN 50000
#define EE 640000
#define HH 128

// ---------------- device scratch (static, no allocs) ----------------
__device__ __align__(16) float g_z[NN * HH];     // encoder output
__device__ __align__(16) float g_A[NN * HH];     // z @ W_M[0:128]   (+ b_M folded)
__device__ __align__(16) float g_B[NN * HH];     // z @ W_M[128:256]
__device__ __align__(16) float g_agg[NN * HH];   // segment max result
__device__ int   g_counts[NN];
__device__ int   g_offsets[NN + 1];
__device__ int   g_cursor[NN];
__device__ int   g_ssrc[EE];
__device__ __align__(16) float g_sattr_buf[EE];
__device__ float g_hsum[HH];

// ---------------- init: zero counts + hsum ----------------
__global__ void init_kernel() {
    int i = blockIdx.x * blockDim.x + threadIdx.x;
    if (i < NN) g_counts[i] = 0;
    if (i < HH) g_hsum[i] = 0.f;
}

// ---------------- generic fp32 GEMM: C[M,128] = act( X(K) @ W[K,128] + bias (+ xcol*w0) )
// X: k<128 from X0, k>=128 from X1 (both row-stride 128). TM=64 rows/block, 256 threads.
__global__ __launch_bounds__(256)
void gemm128_kernel(const float* __restrict__ X0, const float* __restrict__ X1,
                    int K,
                    const float* __restrict__ W,      // [K,128] row-major
                    const float* __restrict__ bias,   // [128] or null
                    const float* __restrict__ xcol,   // [M] or null (rank-1 term)
                    const float* __restrict__ w0,     // [128] or null
                    float* __restrict__ C, int M, int doRelu)
{
    const int TM = 64, TK = 16;
    __shared__ float Xs[TM][TK + 1];
    __shared__ float Ws[TK][HH];

    int tid  = threadIdx.x;
    int row0 = blockIdx.x * TM;
    int tc   = tid & 31;   // col group: cols tc*4 .. tc*4+3
    int tr   = tid >> 5;   // warp id: rows tr*8 .. tr*8+7

    float acc[8][4];
#pragma unroll
    for (int r = 0; r < 8; r++) { acc[r][0]=0.f; acc[r][1]=0.f; acc[r][2]=0.f; acc[r][3]=0.f; }

    for (int kc = 0; kc < K; kc += TK) {
        // load X tile: 64 rows x 16 k, each thread one float4
        {
            int r  = tid >> 2;
            int kk = (tid & 3) * 4;
            int grow = row0 + r;
            const float* Xsrc = (kc < HH) ? X0 : X1;
            int gk = (kc < HH) ? (kc + kk) : (kc - HH + kk);
            float4 v = make_float4(0.f, 0.f, 0.f, 0.f);
            if (grow < M) v = *(const float4*)(Xsrc + (size_t)grow * HH + gk);
            Xs[r][kk+0]=v.x; Xs[r][kk+1]=v.y; Xs[r][kk+2]=v.z; Xs[r][kk+3]=v.w;
        }
        // load W tile: 16 x 128, each thread two float4
        {
#pragma unroll
            for (int i = 0; i < 2; i++) {
                int idx = tid + i * 256;       // 0..511 float4s
                int k = idx >> 5;
                int c = (idx & 31) * 4;
                float4 v = *(const float4*)(W + (size_t)(kc + k) * HH + c);
                *(float4*)&Ws[k][c] = v;
            }
        }
        __syncthreads();
#pragma unroll
        for (int k = 0; k < TK; k++) {
            float4 w4 = *(const float4*)&Ws[k][tc * 4];
#pragma unroll
            for (int r = 0; r < 8; r++) {
                float xv = Xs[tr * 8 + r][k];
                acc[r][0] = fmaf(xv, w4.x, acc[r][0]);
                acc[r][1] = fmaf(xv, w4.y, acc[r][1]);
                acc[r][2] = fmaf(xv, w4.z, acc[r][2]);
                acc[r][3] = fmaf(xv, w4.w, acc[r][3]);
            }
        }
        __syncthreads();
    }

    int c0 = tc * 4;
    float4 bv  = make_float4(0.f,0.f,0.f,0.f);
    float4 w0v = make_float4(0.f,0.f,0.f,0.f);
    if (bias) bv  = *(const float4*)(bias + c0);
    if (w0)   w0v = *(const float4*)(w0 + c0);

#pragma unroll
    for (int r = 0; r < 8; r++) {
        int grow = row0 + tr * 8 + r;
        if (grow < M) {
            float xs = xcol ? xcol[grow] : 0.f;
            float4 o;
            o.x = fmaf(xs, w0v.x, acc[r][0] + bv.x);
            o.y = fmaf(xs, w0v.y, acc[r][1] + bv.y);
            o.z = fmaf(xs, w0v.z, acc[r][2] + bv.z);
            o.w = fmaf(xs, w0v.w, acc[r][3] + bv.w);
            if (doRelu) {
                o.x = fmaxf(o.x, 0.f); o.y = fmaxf(o.y, 0.f);
                o.z = fmaxf(o.z, 0.f); o.w = fmaxf(o.w, 0.f);
            }
            *(float4*)(C + (size_t)grow * HH + c0) = o;
        }
    }
}

// ---------------- CSR build ----------------
__global__ void hist_kernel(const int* __restrict__ dst) {
    int e = blockIdx.x * blockDim.x + threadIdx.x;
    if (e < EE) atomicAdd(&g_counts[dst[e]], 1);
}

__global__ void scan_kernel() {
    __shared__ int part[1024];
    int t = threadIdx.x;
    const int CH = (NN + 1023) / 1024;   // 49
    int base = t * CH;
    int s = 0;
    for (int i = 0; i < CH; i++) { int idx = base + i; if (idx < NN) s += g_counts[idx]; }
    part[t] = s; __syncthreads();
    for (int off = 1; off < 1024; off <<= 1) {
        int v = (t >= off) ? part[t - off] : 0;
        __syncthreads();
        part[t] += v;
        __syncthreads();
    }
    int run = (t == 0) ? 0 : part[t - 1];
    for (int i = 0; i < CH; i++) {
        int idx = base + i;
        if (idx < NN) { g_offsets[idx] = run; g_cursor[idx] = run; run += g_counts[idx]; }
    }
    if (t == 0) g_offsets[NN] = part[1023];
}

__global__ void scatter_kernel(const int* __restrict__ src, const int* __restrict__ dst,
                               const float* __restrict__ attr) {
    int e = blockIdx.x * blockDim.x + threadIdx.x;
    if (e < EE) {
        int d = dst[e];
        int pos = atomicAdd(&g_cursor[d], 1);
        g_ssrc[pos] = src[e];
        g_sattr_buf[pos] = attr[e];
    }
}

// ---------------- per-node edge max: warp per node ----------------
__global__ __launch_bounds__(256)
void agg_kernel(const float* __restrict__ W_M) {
    int node = blockIdx.x * 8 + (threadIdx.x >> 5);
    if (node >= NN) return;
    int lane = threadIdx.x & 31;
    int c = lane * 4;
    float4 w4 = *(const float4*)(W_M + 256 * HH + c);  // attr row of W_M
    float4 rm = make_float4(-1e30f, -1e30f, -1e30f, -1e30f);
    int e0 = g_offsets[node], e1 = g_offsets[node + 1];
    for (int e = e0; e < e1; e++) {
        int s = g_ssrc[e];
        float a = g_sattr_buf[e];
        float4 b4 = *(const float4*)(g_B + (size_t)s * HH + c);
        rm.x = fmaxf(rm.x, fmaf(a, w4.x, b4.x));
        rm.y = fmaxf(rm.y, fmaf(a, w4.y, b4.y));
        rm.z = fmaxf(rm.z, fmaf(a, w4.z, b4.z));
        rm.w = fmaxf(rm.w, fmaf(a, w4.w, b4.w));
    }
    float4 a4 = *(const float4*)(g_A + (size_t)node * HH + c);   // A already has b_M
    float4 o;
    o.x = fmaxf(a4.x + rm.x, 0.f);
    o.y = fmaxf(a4.y + rm.y, 0.f);
    o.z = fmaxf(a4.z + rm.z, 0.f);
    o.w = fmaxf(a4.w + rm.w, 0.f);
    *(float4*)(g_agg + (size_t)node * HH + c) = o;
}

// ---------------- decoder y: warp per node ----------------
__global__ __launch_bounds__(256)
void y_kernel(const float* __restrict__ h, const float* __restrict__ W_dec,
              const float* __restrict__ b_dec, float* __restrict__ y) {
    int node = blockIdx.x * 8 + (threadIdx.x >> 5);
    if (node >= NN) return;
    int lane = threadIdx.x & 31;
    int c = lane * 4;
    float4 z4 = *(const float4*)(g_z + (size_t)node * HH + c);
    float4 h4 = *(const float4*)(h + (size_t)node * HH + c);
    float4 wz = *(const float4*)(W_dec + c);
    float4 wh = *(const float4*)(W_dec + HH + c);
    float s = z4.x * wz.x + z4.y * wz.y + z4.z * wz.z + z4.w * wz.w
            + h4.x * wh.x + h4.y * wh.y + h4.z * wh.z + h4.w * wh.w;
#pragma unroll
    for (int o = 16; o; o >>= 1) s += __shfl_down_sync(0xFFFFFFFFu, s, o);
    if (lane == 0) y[node] = s + b_dec[0];
}

// ---------------- h column sums ----------------
__global__ void hsum_kernel(const float* __restrict__ h) {
    int c = threadIdx.x;  // 128 threads
    float s = 0.f;
    for (int r = blockIdx.x; r < NN; r += gridDim.x) s += h[(size_t)r * HH + c];
    atomicAdd(&g_hsum[c], s);
}

// ---------------- tau: closed form from h_mean ----------------
__global__ void tau_kernel(const float* __restrict__ W_term, const float* __restrict__ b_term,
                           float* __restrict__ tau) {
    __shared__ float sm[128];
    int t = threadIdx.x;
    float v = g_hsum[t] * (1.0f / (float)NN) * (W_term[t] + W_term[t + HH]);
    sm[t] = v; __syncthreads();
    for (int o = 64; o; o >>= 1) { if (t < o) sm[t] += sm[t + o]; __syncthreads(); }
    if (t == 0) tau[0] = sm[0] + b_term[0];
}

// ---------------- launch ----------------
extern "C" void kernel_launch(void* const* d_in, const int* in_sizes, int n_in,
                              void* d_out, int out_size)
{
    const float* x         = (const float*)d_in[0];   // [N,1]
    const float* pre_h     = (const float*)d_in[1];   // [N,128]
    const int*   edge_idx  = (const int*)  d_in[2];   // [2,E]
    const float* edge_attr = (const float*)d_in[3];   // [E,1]
    const float* W_enc     = (const float*)d_in[4];   // [129,128]
    const float* b_enc     = (const float*)d_in[5];   // [128]
    const float* W_M       = (const float*)d_in[6];   // [257,128]
    const float* b_M       = (const float*)d_in[7];   // [128]
    const float* W_U       = (const float*)d_in[8];   // [256,128]
    const float* b_U       = (const float*)d_in[9];   // [128]
    const float* W_dec     = (const float*)d_in[10];  // [256,1]
    const float* b_dec     = (const float*)d_in[11];  // [1]
    const float* W_term    = (const float*)d_in[12];  // [256,1]
    const float* b_term    = (const float*)d_in[13];  // [1]

    float* out   = (float*)d_out;
    float* h_out = out;                 // [N,128]
    float* y_out = out + (size_t)NN * HH;  // [N]
    float* tau_o = out + (size_t)NN * HH + NN;  // [1]

    const int* src = edge_idx;
    const int* dst = edge_idx + EE;

    // symbol addresses (device pointers for kernels that need scratch as args)
    float* z_p;   cudaGetSymbolAddress((void**)&z_p,   g_z);
    float* A_p;   cudaGetSymbolAddress((void**)&A_p,   g_A);
    float* B_p;   cudaGetSymbolAddress((void**)&B_p,   g_B);
    float* agg_p; cudaGetSymbolAddress((void**)&agg_p, g_agg);

    int gemmBlocks = (NN + 63) / 64;           // 782
    int eBlocks    = (EE + 255) / 256;         // 2500
    int nWarpBlocks = (NN + 7) / 8;            // 6250

    // 0) init
    init_kernel<<<(NN + 255) / 256, 256>>>();

    // 1) encoder: z = relu(pre_h @ W_enc[1:129] + x * W_enc[0] + b_enc)
    gemm128_kernel<<<gemmBlocks, 256>>>(pre_h, nullptr, 128,
                                        W_enc + HH, b_enc, x, W_enc,
                                        z_p, NN, 1);

    // 2) A = z @ W_M[0:128] + b_M ;  B = z @ W_M[128:256]
    gemm128_kernel<<<gemmBlocks, 256>>>(z_p, nullptr, 128,
                                        W_M, b_M, nullptr, nullptr,
                                        A_p, NN, 0);
    gemm128_kernel<<<gemmBlocks, 256>>>(z_p, nullptr, 128,
                                        W_M + 128 * HH, nullptr, nullptr, nullptr,
                                        B_p, NN, 0);

    // 3) CSR build
    hist_kernel<<<eBlocks, 256>>>(dst);
    scan_kernel<<<1, 1024>>>();
    scatter_kernel<<<eBlocks, 256>>>(src, dst, edge_attr);

    // 4) per-node segment max -> agg
    agg_kernel<<<nWarpBlocks, 256>>>(W_M);

    // 5) update: h = relu([z, agg] @ W_U + b_U)  -> directly into d_out
    gemm128_kernel<<<gemmBlocks, 256>>>(z_p, agg_p, 256,
                                        W_U, b_U, nullptr, nullptr,
                                        h_out, NN, 1);

    // 6) decoder y = [z, h] @ W_dec + b_dec
    y_kernel<<<nWarpBlocks, 256>>>(h_out, W_dec, b_dec, y_out);

    // 7) h column sums + tau closed form
    hsum_kernel<<<256, 128>>>(h_out);
    tau_kernel<<<1, 128>>>(W_term, b_term, tau_o);
}

// round 3
// speedup vs baseline: 1.6742x; 1.6742x over previous
#include <cuda_runtime.h>
#include <cuda_bf16.h>
#include <cstdint>

#define NN 50000
#define EE 640000
#define HH 128

// ============================ device scratch ============================
__device__ __align__(16) float g_z[NN * HH];
__device__ __align__(16) float g_A[NN * HH];
__device__ __align__(16) float g_B[NN * HH];
__device__ __align__(16) float g_agg[NN * HH];
__device__ int   g_counts[NN];
__device__ int   g_offsets[NN + 1];
__device__ int   g_cursor[NN];
__device__ int   g_ssrc[EE];
__device__ __align__(16) float g_sattr_buf[EE];
__device__ float g_hsum[HH];
// pre-split, pre-transposed weights: [n][k] bf16
__device__ __align__(4) __nv_bfloat16 g_Wenc_h[128 * 128], g_Wenc_l[128 * 128];
__device__ __align__(4) __nv_bfloat16 g_Wmsg_h[256 * 128], g_Wmsg_l[256 * 128];
__device__ __align__(4) __nv_bfloat16 g_Wupd_h[128 * 256], g_Wupd_l[128 * 256];

// ============================ helpers ============================
__device__ __forceinline__ uint32_t smem_u32(const void* p) {
    uint32_t a;
    asm("{ .reg .u64 t; cvta.to.shared.u64 t, %1; cvt.u32.u64 %0, t; }" : "=r"(a) : "l"(p));
    return a;
}

__device__ __forceinline__ void ldm_x4(uint32_t* d, uint32_t addr) {
    asm volatile("ldmatrix.sync.aligned.m8n8.x4.shared.b16 {%0,%1,%2,%3}, [%4];"
                 : "=r"(d[0]), "=r"(d[1]), "=r"(d[2]), "=r"(d[3]) : "r"(addr));
}

__device__ __forceinline__ void mma_bf16(float* c, const uint32_t* a, const uint32_t* b) {
    asm volatile(
        "mma.sync.aligned.m16n8k16.row.col.f32.bf16.bf16.f32 "
        "{%0,%1,%2,%3}, {%4,%5,%6,%7}, {%8,%9}, {%0,%1,%2,%3};"
        : "+f"(c[0]), "+f"(c[1]), "+f"(c[2]), "+f"(c[3])
        : "r"(a[0]), "r"(a[1]), "r"(a[2]), "r"(a[3]), "r"(b[0]), "r"(b[1]));
}

// ============================ init ============================
__global__ void init_kernel() {
    int i = blockIdx.x * blockDim.x + threadIdx.x;
    if (i < NN) g_counts[i] = 0;
    if (i < HH) g_hsum[i] = 0.f;
}

// ============================ weight prep: transpose + bf16 split ============================
__device__ __forceinline__ void split_store(float v, __nv_bfloat16* ph, __nv_bfloat16* pl, int idx) {
    __nv_bfloat16 h = __float2bfloat16(v);
    ph[idx] = h;
    pl[idx] = __float2bfloat16(v - __bfloat162float(h));
}

__global__ void prep_w_kernel(const float* __restrict__ W_enc,
                              const float* __restrict__ W_M,
                              const float* __restrict__ W_U) {
    int i = blockIdx.x * blockDim.x + threadIdx.x;
    if (i < 16384) {                       // enc: [128n][128k] from W_enc[1+k][n]
        int n = i >> 7, k = i & 127;
        split_store(W_enc[(1 + k) * 128 + n], g_Wenc_h, g_Wenc_l, n * 128 + k);
    } else if (i < 49152) {                // msg: [256n][128k]
        int j = i - 16384;
        int n = j >> 7, k = j & 127;
        float v = (n < 128) ? W_M[k * 128 + n] : W_M[(128 + k) * 128 + (n - 128)];
        split_store(v, g_Wmsg_h, g_Wmsg_l, n * 128 + k);
    } else if (i < 81920) {                // upd: [128n][256k] from W_U[k][n]
        int j = i - 49152;
        int n = j >> 8, k = j & 255;
        split_store(W_U[k * 128 + n], g_Wupd_h, g_Wupd_l, n * 256 + k);
    }
}

// ============================ mma.sync bf16 split GEMM ============================
// C[M, 128*gridDim.y] = act( X[M,K] @ W + bias (+ xcol*w0) )
// X: chunk 0 from X0, chunk 1 from X1 (fp32, row stride 128). W pre-split [n][K] bf16.
// CTA tile 128(M) x 128(N). 256 threads = 8 warps as 2(M) x 4(N), warp tile 64x32.
// smem pitch: 272 bytes per row (136 bf16) -> conflict-free ldmatrix.
#define PITCHB 272
#define SM_XH 0
#define SM_XL 34816
#define SM_WH 69632
#define SM_WL 104448
#define SM_TOTAL 139264

__global__ __launch_bounds__(256, 1)
void gemm_mma(const float* __restrict__ X0, const float* __restrict__ X1, int K,
              const __nv_bfloat16* __restrict__ Wh, const __nv_bfloat16* __restrict__ Wl,
              const float* __restrict__ bias0, const float* __restrict__ bias1,
              const float* __restrict__ xcol, const float* __restrict__ w0,
              float* __restrict__ C0, float* __restrict__ C1,
              int M, int doRelu)
{
    extern __shared__ char smem[];
    const uint32_t sb = smem_u32(smem);
    const int tid  = threadIdx.x;
    const int warp = tid >> 5;
    const int lane = tid & 31;
    const int warp_m = warp >> 2;        // 0..1 -> rows warp_m*64
    const int warp_n = warp & 3;         // 0..3 -> cols warp_n*32
    const int row0 = blockIdx.x * 128;
    const int nb   = blockIdx.y;         // output 128-col block

    float acc[4][4][4];
#pragma unroll
    for (int mt = 0; mt < 4; mt++)
#pragma unroll
        for (int nt = 0; nt < 4; nt++)
#pragma unroll
            for (int j = 0; j < 4; j++) acc[mt][nt][j] = 0.f;

    const int nchunks = K >> 7;

    // precomputed ldmatrix lane addressing
    const int a_r   = (lane & 7) + ((lane & 8) ? 8 : 0);
    const int a_ko  = (lane & 16) ? 16 : 0;
    const int b_n   = (lane & 7) + ((lane & 16) ? 8 : 0);
    const int b_ko  = (lane & 8) ? 16 : 0;

    for (int c = 0; c < nchunks; c++) {
        // ---- load X chunk [128 rows x 128 k] fp32 -> bf16 hi/lo ----
        const float* Xsrc = (c == 0) ? X0 : X1;
        for (int idx = tid; idx < 128 * 64; idx += 256) {
            int row = idx >> 6;
            int k   = (idx & 63) * 2;
            int grow = row0 + row;
            float2 v = make_float2(0.f, 0.f);
            if (grow < M) v = *(const float2*)(Xsrc + (size_t)grow * 128 + k);
            __nv_bfloat16 hx = __float2bfloat16(v.x), hy = __float2bfloat16(v.y);
            __nv_bfloat16 lx = __float2bfloat16(v.x - __bfloat162float(hx));
            __nv_bfloat16 ly = __float2bfloat16(v.y - __bfloat162float(hy));
            uint32_t hh = (uint32_t)__bfloat16_as_ushort(hx) | ((uint32_t)__bfloat16_as_ushort(hy) << 16);
            uint32_t ll = (uint32_t)__bfloat16_as_ushort(lx) | ((uint32_t)__bfloat16_as_ushort(ly) << 16);
            uint32_t off = (uint32_t)row * PITCHB + (uint32_t)k * 2;
            *(uint32_t*)(smem + SM_XH + off) = hh;
            *(uint32_t*)(smem + SM_XL + off) = ll;
        }
        // ---- load W chunk [128 n x 128 k] bf16 (pre-split) ----
        for (int idx = tid; idx < 128 * 64; idx += 256) {
            int n = idx >> 6;
            int k = (idx & 63) * 2;
            size_t go = (size_t)(nb * 128 + n) * K + (size_t)(c << 7) + k;
            uint32_t hh = *(const uint32_t*)(Wh + go);
            uint32_t ll = *(const uint32_t*)(Wl + go);
            uint32_t off = (uint32_t)n * PITCHB + (uint32_t)k * 2;
            *(uint32_t*)(smem + SM_WH + off) = hh;
            *(uint32_t*)(smem + SM_WL + off) = ll;
        }
        __syncthreads();

        // ---- 8 k-steps of ldmatrix + mma ----
        for (int ks = 0; ks < 8; ks++) {
            const uint32_t kb = (uint32_t)ks * 32;
            uint32_t ah[4][4], al[4][4];
#pragma unroll
            for (int mt = 0; mt < 4; mt++) {
                uint32_t addr = sb + SM_XH
                              + (uint32_t)(warp_m * 64 + mt * 16 + a_r) * PITCHB
                              + kb + (uint32_t)a_ko;
                ldm_x4(ah[mt], addr);
                ldm_x4(al[mt], addr + (SM_XL - SM_XH));
            }
            uint32_t bh[4][2], bl[4][2];
#pragma unroll
            for (int g = 0; g < 2; g++) {
                uint32_t addr = sb + SM_WH
                              + (uint32_t)(warp_n * 32 + g * 16 + b_n) * PITCHB
                              + kb + (uint32_t)b_ko;
                uint32_t t[4];
                ldm_x4(t, addr);
                bh[2*g][0] = t[0]; bh[2*g][1] = t[1];
                bh[2*g+1][0] = t[2]; bh[2*g+1][1] = t[3];
                ldm_x4(t, addr + (SM_WL - SM_WH));
                bl[2*g][0] = t[0]; bl[2*g][1] = t[1];
                bl[2*g+1][0] = t[2]; bl[2*g+1][1] = t[3];
            }
#pragma unroll
            for (int mt = 0; mt < 4; mt++)
#pragma unroll
                for (int nt = 0; nt < 4; nt++) {
                    mma_bf16(acc[mt][nt], ah[mt], bh[nt]);
                    mma_bf16(acc[mt][nt], ah[mt], bl[nt]);
                    mma_bf16(acc[mt][nt], al[mt], bh[nt]);
                }
        }
        __syncthreads();
    }

    // ---- epilogue ----
    const float* bp = (nb == 0) ? bias0 : bias1;
    float*       Cp = (nb == 0) ? C0 : C1;
#pragma unroll
    for (int mt = 0; mt < 4; mt++) {
#pragma unroll
        for (int nt = 0; nt < 4; nt++) {
            int rg  = row0 + warp_m * 64 + mt * 16 + (lane >> 2);
            int col = warp_n * 32 + nt * 8 + (lane & 3) * 2;
            float b0 = 0.f, b1 = 0.f, w00 = 0.f, w01 = 0.f;
            if (bp) { b0 = bp[col]; b1 = bp[col + 1]; }
            if (w0) { w00 = w0[col]; w01 = w0[col + 1]; }
            if (rg < M) {
                float xv = xcol ? xcol[rg] : 0.f;
                float o0 = fmaf(xv, w00, acc[mt][nt][0] + b0);
                float o1 = fmaf(xv, w01, acc[mt][nt][1] + b1);
                if (doRelu) { o0 = fmaxf(o0, 0.f); o1 = fmaxf(o1, 0.f); }
                *(float2*)(Cp + (size_t)rg * 128 + col) = make_float2(o0, o1);
            }
            int rg8 = rg + 8;
            if (rg8 < M) {
                float xv = xcol ? xcol[rg8] : 0.f;
                float o0 = fmaf(xv, w00, acc[mt][nt][2] + b0);
                float o1 = fmaf(xv, w01, acc[mt][nt][3] + b1);
                if (doRelu) { o0 = fmaxf(o0, 0.f); o1 = fmaxf(o1, 0.f); }
                *(float2*)(Cp + (size_t)rg8 * 128 + col) = make_float2(o0, o1);
            }
        }
    }
}

// ============================ CSR build ============================
__global__ void hist_kernel(const int* __restrict__ dst) {
    int e = blockIdx.x * blockDim.x + threadIdx.x;
    if (e < EE) atomicAdd(&g_counts[dst[e]], 1);
}

__global__ void scan_kernel() {
    __shared__ int part[1024];
    int t = threadIdx.x;
    const int CH = (NN + 1023) / 1024;
    int base = t * CH;
    int s = 0;
    for (int i = 0; i < CH; i++) { int idx = base + i; if (idx < NN) s += g_counts[idx]; }
    part[t] = s; __syncthreads();
    for (int off = 1; off < 1024; off <<= 1) {
        int v = (t >= off) ? part[t - off] : 0;
        __syncthreads();
        part[t] += v;
        __syncthreads();
    }
    int run = (t == 0) ? 0 : part[t - 1];
    for (int i = 0; i < CH; i++) {
        int idx = base + i;
        if (idx < NN) { g_offsets[idx] = run; g_cursor[idx] = run; run += g_counts[idx]; }
    }
    if (t == 0) g_offsets[NN] = part[1023];
}

__global__ void scatter_kernel(const int* __restrict__ src, const int* __restrict__ dst,
                               const float* __restrict__ attr) {
    int e = blockIdx.x * blockDim.x + threadIdx.x;
    if (e < EE) {
        int d = dst[e];
        int pos = atomicAdd(&g_cursor[d], 1);
        g_ssrc[pos] = src[e];
        g_sattr_buf[pos] = attr[e];
    }
}

// ============================ per-node edge max ============================
__global__ __launch_bounds__(256)
void agg_kernel(const float* __restrict__ W_M) {
    int node = blockIdx.x * 8 + (threadIdx.x >> 5);
    if (node >= NN) return;
    int lane = threadIdx.x & 31;
    int c = lane * 4;
    float4 w4 = *(const float4*)(W_M + 256 * HH + c);
    float4 rm = make_float4(-1e30f, -1e30f, -1e30f, -1e30f);
    int e0 = g_offsets[node], e1 = g_offsets[node + 1];
    for (int e = e0; e < e1; e++) {
        int s = g_ssrc[e];
        float a = g_sattr_buf[e];
        float4 b4 = *(const float4*)(g_B + (size_t)s * HH + c);
        rm.x = fmaxf(rm.x, fmaf(a, w4.x, b4.x));
        rm.y = fmaxf(rm.y, fmaf(a, w4.y, b4.y));
        rm.z = fmaxf(rm.z, fmaf(a, w4.z, b4.z));
        rm.w = fmaxf(rm.w, fmaf(a, w4.w, b4.w));
    }
    float4 a4 = *(const float4*)(g_A + (size_t)node * HH + c);
    float4 o;
    o.x = fmaxf(a4.x + rm.x, 0.f);
    o.y = fmaxf(a4.y + rm.y, 0.f);
    o.z = fmaxf(a4.z + rm.z, 0.f);
    o.w = fmaxf(a4.w + rm.w, 0.f);
    *(float4*)(g_agg + (size_t)node * HH + c) = o;
}

// ============================ decoder y ============================
__global__ __launch_bounds__(256)
void y_kernel(const float* __restrict__ h, const float* __restrict__ W_dec,
              const float* __restrict__ b_dec, float* __restrict__ y) {
    int node = blockIdx.x * 8 + (threadIdx.x >> 5);
    if (node >= NN) return;
    int lane = threadIdx.x & 31;
    int c = lane * 4;
    float4 z4 = *(const float4*)(g_z + (size_t)node * HH + c);
    float4 h4 = *(const float4*)(h + (size_t)node * HH + c);
    float4 wz = *(const float4*)(W_dec + c);
    float4 wh = *(const float4*)(W_dec + HH + c);
    float s = z4.x * wz.x + z4.y * wz.y + z4.z * wz.z + z4.w * wz.w
            + h4.x * wh.x + h4.y * wh.y + h4.z * wh.z + h4.w * wh.w;
#pragma unroll
    for (int o = 16; o; o >>= 1) s += __shfl_down_sync(0xFFFFFFFFu, s, o);
    if (lane == 0) y[node] = s + b_dec[0];
}

// ============================ h column sums + tau ============================
__global__ void hsum_kernel(const float* __restrict__ h) {
    int c = threadIdx.x;
    float s = 0.f;
    for (int r = blockIdx.x; r < NN; r += gridDim.x) s += h[(size_t)r * HH + c];
    atomicAdd(&g_hsum[c], s);
}

__global__ void tau_kernel(const float* __restrict__ W_term, const float* __restrict__ b_term,
                           float* __restrict__ tau) {
    __shared__ float sm[128];
    int t = threadIdx.x;
    float v = g_hsum[t] * (1.0f / (float)NN) * (W_term[t] + W_term[t + HH]);
    sm[t] = v; __syncthreads();
    for (int o = 64; o; o >>= 1) { if (t < o) sm[t] += sm[t + o]; __syncthreads(); }
    if (t == 0) tau[0] = sm[0] + b_term[0];
}

// ============================ launch ============================
extern "C" void kernel_launch(void* const* d_in, const int* in_sizes, int n_in,
                              void* d_out, int out_size)
{
    const float* x         = (const float*)d_in[0];
    const float* pre_h     = (const float*)d_in[1];
    const int*   edge_idx  = (const int*)  d_in[2];
    const float* edge_attr = (const float*)d_in[3];
    const float* W_enc     = (const float*)d_in[4];
    const float* b_enc     = (const float*)d_in[5];
    const float* W_M       = (const float*)d_in[6];
    const float* b_M       = (const float*)d_in[7];
    const float* W_U       = (const float*)d_in[8];
    const float* b_U       = (const float*)d_in[9];
    const float* W_dec     = (const float*)d_in[10];
    const float* b_dec     = (const float*)d_in[11];
    const float* W_term    = (const float*)d_in[12];
    const float* b_term    = (const float*)d_in[13];

    float* out   = (float*)d_out;
    float* h_out = out;
    float* y_out = out + (size_t)NN * HH;
    float* tau_o = out + (size_t)NN * HH + NN;

    const int* src = edge_idx;
    const int* dst = edge_idx + EE;

    float* z_p;   cudaGetSymbolAddress((void**)&z_p,   g_z);
    float* A_p;   cudaGetSymbolAddress((void**)&A_p,   g_A);
    float* B_p;   cudaGetSymbolAddress((void**)&B_p,   g_B);
    float* agg_p; cudaGetSymbolAddress((void**)&agg_p, g_agg);
    __nv_bfloat16 *wench, *wencl, *wmsgh, *wmsgl, *wupdh, *wupdl;
    cudaGetSymbolAddress((void**)&wench, g_Wenc_h);
    cudaGetSymbolAddress((void**)&wencl, g_Wenc_l);
    cudaGetSymbolAddress((void**)&wmsgh, g_Wmsg_h);
    cudaGetSymbolAddress((void**)&wmsgl, g_Wmsg_l);
    cudaGetSymbolAddress((void**)&wupdh, g_Wupd_h);
    cudaGetSymbolAddress((void**)&wupdl, g_Wupd_l);

    cudaFuncSetAttribute(gemm_mma, cudaFuncAttributeMaxDynamicSharedMemorySize, SM_TOTAL);

    const int gemmGridX   = (NN + 127) / 128;   // 391
    const int eBlocks     = (EE + 255) / 256;
    const int nWarpBlocks = (NN + 7) / 8;

    // 0) init + weight prep
    init_kernel<<<(NN + 255) / 256, 256>>>();
    prep_w_kernel<<<320, 256>>>(W_enc, W_M, W_U);

    // 1) encoder: z = relu(pre_h @ W_enc[1:] + x * W_enc[0] + b_enc)
    gemm_mma<<<dim3(gemmGridX, 1), 256, SM_TOTAL>>>(
        pre_h, nullptr, 128, wench, wencl,
        b_enc, nullptr, x, W_enc, z_p, nullptr, NN, 1);

    // 2) fused msg: [A | B] = z @ [W_M1 | W_M2], A gets +b_M
    gemm_mma<<<dim3(gemmGridX, 2), 256, SM_TOTAL>>>(
        z_p, nullptr, 128, wmsgh, wmsgl,
        b_M, nullptr, nullptr, nullptr, A_p, B_p, NN, 0);

    // 3) CSR build
    hist_kernel<<<eBlocks, 256>>>(dst);
    scan_kernel<<<1, 1024>>>();
    scatter_kernel<<<eBlocks, 256>>>(src, dst, edge_attr);

    // 4) per-node segment max
    agg_kernel<<<nWarpBlocks, 256>>>(W_M);

    // 5) update: h = relu([z, agg] @ W_U + b_U)
    gemm_mma<<<dim3(gemmGridX, 1), 256, SM_TOTAL>>>(
        z_p, agg_p, 256, wupdh, wupdl,
        b_U, nullptr, nullptr, nullptr, h_out, nullptr, NN, 1);

    // 6) decoder + terminator
    y_kernel<<<nWarpBlocks, 256>>>(h_out, W_dec, b_dec, y_out);
    hsum_kernel<<<256, 128>>>(h_out);
    tau_kernel<<<1, 128>>>(W_term, b_term, tau_o);
}

// round 4
// speedup vs baseline: 2.1176x; 1.2649x over previous
#include <cuda_runtime.h>
#include <cuda_bf16.h>
#include <cstdint>

#define NN 50000
#define EE 640000
#define HH 128

// ============================ device scratch ============================
__device__ __align__(16) float g_z[NN * HH];
__device__ __align__(16) float g_Amat[NN * HH];
__device__ __align__(16) float g_Bmat[NN * HH];
__device__ int   g_counts[NN];
__device__ int   g_offsets[NN + 1];
__device__ int   g_cursor[NN];
__device__ __align__(16) int2 g_sedge[EE];
__device__ float g_hsum[HH];
// pre-split bf16 activations (hi/lo)
__device__ __align__(16) __nv_bfloat16 g_ph_h[NN * HH], g_ph_l[NN * HH];
__device__ __align__(16) __nv_bfloat16 g_z_h[NN * HH],  g_z_l[NN * HH];
__device__ __align__(16) __nv_bfloat16 g_ag_h[NN * HH], g_ag_l[NN * HH];
// pre-split, pre-transposed weights: [n][k] bf16
__device__ __align__(16) __nv_bfloat16 g_Wenc_h[128 * 128], g_Wenc_l[128 * 128];
__device__ __align__(16) __nv_bfloat16 g_Wmsg_h[256 * 128], g_Wmsg_l[256 * 128];
__device__ __align__(16) __nv_bfloat16 g_Wupd_h[128 * 256], g_Wupd_l[128 * 256];

// ============================ helpers ============================
__device__ __forceinline__ uint32_t smem_u32(const void* p) {
    uint32_t a;
    asm("{ .reg .u64 t; cvta.to.shared.u64 t, %1; cvt.u32.u64 %0, t; }" : "=r"(a) : "l"(p));
    return a;
}
__device__ __forceinline__ void ldm_x4(uint32_t* d, uint32_t addr) {
    asm volatile("ldmatrix.sync.aligned.m8n8.x4.shared.b16 {%0,%1,%2,%3}, [%4];"
                 : "=r"(d[0]), "=r"(d[1]), "=r"(d[2]), "=r"(d[3]) : "r"(addr));
}
__device__ __forceinline__ void mma_bf16(float* c, const uint32_t* a, const uint32_t* b) {
    asm volatile(
        "mma.sync.aligned.m16n8k16.row.col.f32.bf16.bf16.f32 "
        "{%0,%1,%2,%3}, {%4,%5,%6,%7}, {%8,%9}, {%0,%1,%2,%3};"
        : "+f"(c[0]), "+f"(c[1]), "+f"(c[2]), "+f"(c[3])
        : "r"(a[0]), "r"(a[1]), "r"(a[2]), "r"(a[3]), "r"(b[0]), "r"(b[1]));
}
#define CP16(d, s, sz) asm volatile("cp.async.cg.shared.global [%0], [%1], 16, %2;" \
                                    :: "r"(d), "l"(s), "r"(sz) : "memory")
#define CP_COMMIT() asm volatile("cp.async.commit_group;" ::: "memory")
#define CP_WAIT0()  asm volatile("cp.async.wait_group 0;" ::: "memory")

__device__ __forceinline__ uint32_t pack_hi(float a, float b) {
    __nv_bfloat16 ha = __float2bfloat16(a), hb = __float2bfloat16(b);
    return (uint32_t)__bfloat16_as_ushort(ha) | ((uint32_t)__bfloat16_as_ushort(hb) << 16);
}
__device__ __forceinline__ uint32_t pack_lo(float a, float b) {
    __nv_bfloat16 ha = __float2bfloat16(a), hb = __float2bfloat16(b);
    float ra = a - __bfloat162float(ha), rb = b - __bfloat162float(hb);
    __nv_bfloat16 la = __float2bfloat16(ra), lb = __float2bfloat16(rb);
    return (uint32_t)__bfloat16_as_ushort(la) | ((uint32_t)__bfloat16_as_ushort(lb) << 16);
}

// ============================ init ============================
__global__ void init_kernel() {
    int i = blockIdx.x * blockDim.x + threadIdx.x;
    if (i < NN) g_counts[i] = 0;
    if (i < HH) g_hsum[i] = 0.f;
}

// ============================ weight prep ============================
__device__ __forceinline__ void split_store(float v, __nv_bfloat16* ph, __nv_bfloat16* pl, int idx) {
    __nv_bfloat16 h = __float2bfloat16(v);
    ph[idx] = h;
    pl[idx] = __float2bfloat16(v - __bfloat162float(h));
}
__global__ void prep_w_kernel(const float* __restrict__ W_enc,
                              const float* __restrict__ W_M,
                              const float* __restrict__ W_U) {
    int i = blockIdx.x * blockDim.x + threadIdx.x;
    if (i < 16384) {
        int n = i >> 7, k = i & 127;
        split_store(W_enc[(1 + k) * 128 + n], g_Wenc_h, g_Wenc_l, n * 128 + k);
    } else if (i < 49152) {
        int j = i - 16384;
        int n = j >> 7, k = j & 127;
        float v = (n < 128) ? W_M[k * 128 + n] : W_M[(128 + k) * 128 + (n - 128)];
        split_store(v, g_Wmsg_h, g_Wmsg_l, n * 128 + k);
    } else if (i < 81920) {
        int j = i - 49152;
        int n = j >> 8, k = j & 255;
        split_store(W_U[k * 128 + n], g_Wupd_h, g_Wupd_l, n * 256 + k);
    }
}

// ============================ activation pre-split ============================
__global__ void prep_x_kernel(const float* __restrict__ X,
                              __nv_bfloat16* __restrict__ Xh,
                              __nv_bfloat16* __restrict__ Xl, int npairs) {
    int i = blockIdx.x * blockDim.x + threadIdx.x;
    if (i < npairs) {
        float2 v = ((const float2*)X)[i];
        ((uint32_t*)Xh)[i] = pack_hi(v.x, v.y);
        ((uint32_t*)Xl)[i] = pack_lo(v.x, v.y);
    }
}

// ============================ mma.sync bf16 split GEMM ============================
// CTA tile 128(M) x 64(N); 8 warps as 4M x 2N, warp tile 32x32.
// smem: 256B rows, chunk-XOR swizzle; filled by cp.async from pre-split bf16 gmem.
#define SM_XH 0
#define SM_XL 32768
#define SM_WH 65536
#define SM_WL 81920
#define SM_TOTAL 98304

__global__ __launch_bounds__(256, 2)
void gemm_mma(const __nv_bfloat16* __restrict__ X0h, const __nv_bfloat16* __restrict__ X0l,
              const __nv_bfloat16* __restrict__ X1h, const __nv_bfloat16* __restrict__ X1l,
              int K,
              const __nv_bfloat16* __restrict__ Wh, const __nv_bfloat16* __restrict__ Wl,
              const float* __restrict__ bias0, const float* __restrict__ bias1,
              const float* __restrict__ xcol, const float* __restrict__ w0,
              float* __restrict__ C0, float* __restrict__ C1,
              __nv_bfloat16* __restrict__ Sh, __nv_bfloat16* __restrict__ Sl,
              int M, int doRelu)
{
    extern __shared__ char smem[];
    const uint32_t sb = smem_u32(smem);
    const int tid  = threadIdx.x;
    const int warp = tid >> 5;
    const int lane = tid & 31;
    const int warp_m = warp >> 1;        // 0..3 -> rows warp_m*32
    const int warp_n = warp & 1;         // 0..1 -> cols warp_n*32
    const int row0 = blockIdx.x * 128;
    const int nb   = blockIdx.y;         // 64-col output block
    const int halfIdx = nb >> 1;
    const int colbase = (nb & 1) * 64;

    float acc[2][4][4];
#pragma unroll
    for (int mt = 0; mt < 2; mt++)
#pragma unroll
        for (int nt = 0; nt < 4; nt++)
#pragma unroll
            for (int j = 0; j < 4; j++) acc[mt][nt][j] = 0.f;

    const int nchunks = K >> 7;
    const int a_r = lane & 15;
    const int a_k1 = (lane & 16) ? 1 : 0;
    const int b_n = (lane & 7) + ((lane & 16) ? 8 : 0);
    const int b_k1 = (lane & 8) ? 1 : 0;

    for (int c = 0; c < nchunks; c++) {
        const __nv_bfloat16* Xh = c ? X1h : X0h;
        const __nv_bfloat16* Xl = c ? X1l : X0l;
        // X fill: 128 rows x 16 chunks of 16B, hi+lo
        for (int idx = tid; idx < 2048; idx += 256) {
            int row = idx >> 4, c16 = idx & 15;
            int grow = row0 + row;
            int grc = (grow < M) ? grow : 0;
            uint32_t sz = (grow < M) ? 16u : 0u;
            uint32_t soff = (uint32_t)row * 256 + (uint32_t)((c16 ^ (row & 7)) << 4);
            size_t go = (size_t)grc * 128 + (size_t)c16 * 8;
            CP16(sb + SM_XH + soff, Xh + go, sz);
            CP16(sb + SM_XL + soff, Xl + go, sz);
        }
        // W fill: 64 n-rows x 16 chunks, hi+lo
        for (int idx = tid; idx < 1024; idx += 256) {
            int n = idx >> 4, c16 = idx & 15;
            int gn = nb * 64 + n;
            uint32_t soff = (uint32_t)n * 256 + (uint32_t)((c16 ^ (n & 7)) << 4);
            size_t go = (size_t)gn * K + (size_t)(c << 7) + (size_t)c16 * 8;
            CP16(sb + SM_WH + soff, Wh + go, 16u);
            CP16(sb + SM_WL + soff, Wl + go, 16u);
        }
        CP_COMMIT();
        CP_WAIT0();
        __syncthreads();

#pragma unroll 2
        for (int ks = 0; ks < 8; ks++) {
            const int akc = ks * 2 + a_k1;
            const int bkc = ks * 2 + b_k1;
            uint32_t ah[2][4], al[2][4];
#pragma unroll
            for (int mt = 0; mt < 2; mt++) {
                int r = warp_m * 32 + mt * 16 + a_r;
                uint32_t addr = sb + SM_XH + (uint32_t)r * 256 + (uint32_t)((akc ^ (r & 7)) << 4);
                ldm_x4(ah[mt], addr);
                ldm_x4(al[mt], addr + (SM_XL - SM_XH));
            }
            uint32_t bh[4][2], bl[4][2];
#pragma unroll
            for (int g = 0; g < 2; g++) {
                int n = warp_n * 32 + g * 16 + b_n;
                uint32_t addr = sb + SM_WH + (uint32_t)n * 256 + (uint32_t)((bkc ^ (n & 7)) << 4);
                uint32_t t[4];
                ldm_x4(t, addr);
                bh[2*g][0] = t[0];   bh[2*g][1] = t[1];
                bh[2*g+1][0] = t[2]; bh[2*g+1][1] = t[3];
                ldm_x4(t, addr + (SM_WL - SM_WH));
                bl[2*g][0] = t[0];   bl[2*g][1] = t[1];
                bl[2*g+1][0] = t[2]; bl[2*g+1][1] = t[3];
            }
#pragma unroll
            for (int mt = 0; mt < 2; mt++)
#pragma unroll
                for (int nt = 0; nt < 4; nt++) {
                    mma_bf16(acc[mt][nt], ah[mt], bh[nt]);
                    mma_bf16(acc[mt][nt], ah[mt], bl[nt]);
                    mma_bf16(acc[mt][nt], al[mt], bh[nt]);
                }
        }
        __syncthreads();
    }

    // ---- epilogue ----
    const float* bp = halfIdx ? bias1 : bias0;
    float*       Cp = halfIdx ? C1 : C0;
#pragma unroll
    for (int mt = 0; mt < 2; mt++) {
#pragma unroll
        for (int nt = 0; nt < 4; nt++) {
            int r   = row0 + warp_m * 32 + mt * 16 + (lane >> 2);
            int col = colbase + warp_n * 32 + nt * 8 + (lane & 3) * 2;
            float b0 = 0.f, b1 = 0.f, w00 = 0.f, w01 = 0.f;
            if (bp) { b0 = bp[col]; b1 = bp[col + 1]; }
            if (w0) { w00 = w0[col]; w01 = w0[col + 1]; }
#pragma unroll
            for (int half = 0; half < 2; half++) {
                int rr = r + half * 8;
                if (rr < M) {
                    float xv = xcol ? xcol[rr] : 0.f;
                    float o0 = fmaf(xv, w00, acc[mt][nt][half * 2 + 0] + b0);
                    float o1 = fmaf(xv, w01, acc[mt][nt][half * 2 + 1] + b1);
                    if (doRelu) { o0 = fmaxf(o0, 0.f); o1 = fmaxf(o1, 0.f); }
                    *(float2*)(Cp + (size_t)rr * 128 + col) = make_float2(o0, o1);
                    if (Sh) {
                        size_t so = (size_t)rr * 128 + col;
                        *(uint32_t*)(Sh + so) = pack_hi(o0, o1);
                        *(uint32_t*)(Sl + so) = pack_lo(o0, o1);
                    }
                }
            }
        }
    }
}

// ============================ CSR build ============================
__global__ void hist_kernel(const int* __restrict__ dst) {
    int e = blockIdx.x * blockDim.x + threadIdx.x;
    if (e < EE) atomicAdd(&g_counts[dst[e]], 1);
}

__global__ void scan_kernel() {
    __shared__ int part[1024];
    int t = threadIdx.x;
    const int CH = (NN + 1023) / 1024;
    int base = t * CH;
    int s = 0;
    for (int i = 0; i < CH; i++) { int idx = base + i; if (idx < NN) s += g_counts[idx]; }
    part[t] = s; __syncthreads();
    for (int off = 1; off < 1024; off <<= 1) {
        int v = (t >= off) ? part[t - off] : 0;
        __syncthreads();
        part[t] += v;
        __syncthreads();
    }
    int run = (t == 0) ? 0 : part[t - 1];
    for (int i = 0; i < CH; i++) {
        int idx = base + i;
        if (idx < NN) { g_offsets[idx] = run; g_cursor[idx] = run; run += g_counts[idx]; }
    }
    if (t == 0) g_offsets[NN] = part[1023];
}

__global__ void scatter_kernel(const int* __restrict__ src, const int* __restrict__ dst,
                               const float* __restrict__ attr) {
    int e = blockIdx.x * blockDim.x + threadIdx.x;
    if (e < EE) {
        int d = dst[e];
        int pos = atomicAdd(&g_cursor[d], 1);
        g_sedge[pos] = make_int2(src[e], __float_as_int(attr[e]));
    }
}

// ============================ per-node edge max (writes split bf16) ============================
__global__ __launch_bounds__(256)
void agg_kernel(const float* __restrict__ W_M) {
    int node = blockIdx.x * 8 + (threadIdx.x >> 5);
    if (node >= NN) return;
    int lane = threadIdx.x & 31;
    int c = lane * 4;
    float4 w4 = *(const float4*)(W_M + 256 * HH + c);
    float4 rm = make_float4(-1e30f, -1e30f, -1e30f, -1e30f);
    int e0 = g_offsets[node], e1 = g_offsets[node + 1];
    for (int e = e0; e < e1; e++) {
        int2 p = g_sedge[e];
        int s = p.x;
        float a = __int_as_float(p.y);
        float4 b4 = *(const float4*)(g_Bmat + (size_t)s * HH + c);
        rm.x = fmaxf(rm.x, fmaf(a, w4.x, b4.x));
        rm.y = fmaxf(rm.y, fmaf(a, w4.y, b4.y));
        rm.z = fmaxf(rm.z, fmaf(a, w4.z, b4.z));
        rm.w = fmaxf(rm.w, fmaf(a, w4.w, b4.w));
    }
    float4 a4 = *(const float4*)(g_Amat + (size_t)node * HH + c);
    float4 o;
    o.x = fmaxf(a4.x + rm.x, 0.f);
    o.y = fmaxf(a4.y + rm.y, 0.f);
    o.z = fmaxf(a4.z + rm.z, 0.f);
    o.w = fmaxf(a4.w + rm.w, 0.f);
    size_t so = (size_t)node * HH + c;
    *(uint32_t*)(g_ag_h + so)     = pack_hi(o.x, o.y);
    *(uint32_t*)(g_ag_h + so + 2) = pack_hi(o.z, o.w);
    *(uint32_t*)(g_ag_l + so)     = pack_lo(o.x, o.y);
    *(uint32_t*)(g_ag_l + so + 2) = pack_lo(o.z, o.w);
}

// ============================ decoder y ============================
__global__ __launch_bounds__(256)
void y_kernel(const float* __restrict__ h, const float* __restrict__ W_dec,
              const float* __restrict__ b_dec, float* __restrict__ y) {
    int node = blockIdx.x * 8 + (threadIdx.x >> 5);
    if (node >= NN) return;
    int lane = threadIdx.x & 31;
    int c = lane * 4;
    float4 z4 = *(const float4*)(g_z + (size_t)node * HH + c);
    float4 h4 = *(const float4*)(h + (size_t)node * HH + c);
    float4 wz = *(const float4*)(W_dec + c);
    float4 wh = *(const float4*)(W_dec + HH + c);
    float s = z4.x * wz.x + z4.y * wz.y + z4.z * wz.z + z4.w * wz.w
            + h4.x * wh.x + h4.y * wh.y + h4.z * wh.z + h4.w * wh.w;
#pragma unroll
    for (int o = 16; o; o >>= 1) s += __shfl_down_sync(0xFFFFFFFFu, s, o);
    if (lane == 0) y[node] = s + b_dec[0];
}

// ============================ h column sums + tau ============================
__global__ void hsum_kernel(const float* __restrict__ h) {
    int c = threadIdx.x;
    float s = 0.f;
    for (int r = blockIdx.x; r < NN; r += gridDim.x) s += h[(size_t)r * HH + c];
    atomicAdd(&g_hsum[c], s);
}

__global__ void tau_kernel(const float* __restrict__ W_term, const float* __restrict__ b_term,
                           float* __restrict__ tau) {
    __shared__ float sm[128];
    int t = threadIdx.x;
    float v = g_hsum[t] * (1.0f / (float)NN) * (W_term[t] + W_term[t + HH]);
    sm[t] = v; __syncthreads();
    for (int o = 64; o; o >>= 1) { if (t < o) sm[t] += sm[t + o]; __syncthreads(); }
    if (t == 0) tau[0] = sm[0] + b_term[0];
}

// ============================ launch ============================
extern "C" void kernel_launch(void* const* d_in, const int* in_sizes, int n_in,
                              void* d_out, int out_size)
{
    const float* x         = (const float*)d_in[0];
    const float* pre_h     = (const float*)d_in[1];
    const int*   edge_idx  = (const int*)  d_in[2];
    const float* edge_attr = (const float*)d_in[3];
    const float* W_enc     = (const float*)d_in[4];
    const float* b_enc     = (const float*)d_in[5];
    const float* W_M       = (const float*)d_in[6];
    const float* b_M       = (const float*)d_in[7];
    const float* W_U       = (const float*)d_in[8];
    const float* b_U       = (const float*)d_in[9];
    const float* W_dec     = (const float*)d_in[10];
    const float* b_dec     = (const float*)d_in[11];
    const float* W_term    = (const float*)d_in[12];
    const float* b_term    = (const float*)d_in[13];

    float* out   = (float*)d_out;
    float* h_out = out;
    float* y_out = out + (size_t)NN * HH;
    float* tau_o = out + (size_t)NN * HH + NN;

    const int* src = edge_idx;
    const int* dst = edge_idx + EE;

    float* z_p;  cudaGetSymbolAddress((void**)&z_p,  g_z);
    float* A_p;  cudaGetSymbolAddress((void**)&A_p,  g_Amat);
    float* B_p;  cudaGetSymbolAddress((void**)&B_p,  g_Bmat);
    __nv_bfloat16 *phh, *phl, *zh, *zl, *agh, *agl;
    cudaGetSymbolAddress((void**)&phh, g_ph_h);
    cudaGetSymbolAddress((void**)&phl, g_ph_l);
    cudaGetSymbolAddress((void**)&zh,  g_z_h);
    cudaGetSymbolAddress((void**)&zl,  g_z_l);
    cudaGetSymbolAddress((void**)&agh, g_ag_h);
    cudaGetSymbolAddress((void**)&agl, g_ag_l);
    __nv_bfloat16 *wench, *wencl, *wmsgh, *wmsgl, *wupdh, *wupdl;
    cudaGetSymbolAddress((void**)&wench, g_Wenc_h);
    cudaGetSymbolAddress((void**)&wencl, g_Wenc_l);
    cudaGetSymbolAddress((void**)&wmsgh, g_Wmsg_h);
    cudaGetSymbolAddress((void**)&wmsgl, g_Wmsg_l);
    cudaGetSymbolAddress((void**)&wupdh, g_Wupd_h);
    cudaGetSymbolAddress((void**)&wupdl, g_Wupd_l);

    cudaFuncSetAttribute(gemm_mma, cudaFuncAttributeMaxDynamicSharedMemorySize, SM_TOTAL);

    const int gemmGridX   = (NN + 127) / 128;   // 391
    const int eBlocks     = (EE + 255) / 256;
    const int nWarpBlocks = (NN + 7) / 8;

    // 0) init + weight prep + pre_h split
    init_kernel<<<(NN + 255) / 256, 256>>>();
    prep_w_kernel<<<320, 256>>>(W_enc, W_M, W_U);
    prep_x_kernel<<<(NN * 64 + 255) / 256, 256>>>(pre_h, phh, phl, NN * 64);

    // 1) encoder: z = relu(pre_h @ W_enc[1:] + x * W_enc[0] + b_enc); emits z fp32 + split
    gemm_mma<<<dim3(gemmGridX, 2), 256, SM_TOTAL>>>(
        phh, phl, nullptr, nullptr, 128, wench, wencl,
        b_enc, nullptr, x, W_enc, z_p, nullptr, zh, zl, NN, 1);

    // 2) fused msg: [A | B] = z @ [W_M1 | W_M2], A gets +b_M
    gemm_mma<<<dim3(gemmGridX, 4), 256, SM_TOTAL>>>(
        zh, zl, nullptr, nullptr, 128, wmsgh, wmsgl,
        b_M, nullptr, nullptr, nullptr, A_p, B_p, nullptr, nullptr, NN, 0);

    // 3) CSR build
    hist_kernel<<<eBlocks, 256>>>(dst);
    scan_kernel<<<1, 1024>>>();
    scatter_kernel<<<eBlocks, 256>>>(src, dst, edge_attr);

    // 4) per-node segment max (emits split agg)
    agg_kernel<<<nWarpBlocks, 256>>>(W_M);

    // 5) update: h = relu([z, agg] @ W_U + b_U)
    gemm_mma<<<dim3(gemmGridX, 2), 256, SM_TOTAL>>>(
        zh, zl, agh, agl, 256, wupdh, wupdl,
        b_U, nullptr, nullptr, nullptr, h_out, nullptr, nullptr, nullptr, NN, 1);

    // 6) decoder + terminator
    y_kernel<<<nWarpBlocks, 256>>>(h_out, W_dec, b_dec, y_out);
    hsum_kernel<<<256, 128>>>(h_out);
    tau_kernel<<<1, 128>>>(W_term, b_term, tau_o);
}

// round 5
// speedup vs baseline: 3.2317x; 1.5261x over previous
#include <cuda_runtime.h>
#include <cuda_bf16.h>
#include <cstdint>

#define NN 50000
#define EE 640000
#define HH 128

// ============================ device scratch ============================
__device__ __align__(16) float g_z[NN * HH];
__device__ __align__(16) float g_Amat[NN * HH];
__device__ __align__(16) float g_Bmat[NN * HH];
__device__ int   g_counts[NN];
__device__ int   g_offsets[NN + 1];
__device__ int   g_cursor[NN];
__device__ __align__(16) int2 g_sedge[EE];
__device__ float g_hsum[HH];
// pre-split bf16 activations (hi/lo)
__device__ __align__(16) __nv_bfloat16 g_ph_h[NN * HH], g_ph_l[NN * HH];
__device__ __align__(16) __nv_bfloat16 g_z_h[NN * HH],  g_z_l[NN * HH];
__device__ __align__(16) __nv_bfloat16 g_ag_h[NN * HH], g_ag_l[NN * HH];
// pre-split, pre-transposed weights: [n][k] bf16
__device__ __align__(16) __nv_bfloat16 g_Wenc_h[128 * 128], g_Wenc_l[128 * 128];
__device__ __align__(16) __nv_bfloat16 g_Wmsg_h[256 * 128], g_Wmsg_l[256 * 128];
__device__ __align__(16) __nv_bfloat16 g_Wupd_h[128 * 256], g_Wupd_l[128 * 256];

// ============================ helpers ============================
__device__ __forceinline__ uint32_t smem_u32(const void* p) {
    uint32_t a;
    asm("{ .reg .u64 t; cvta.to.shared.u64 t, %1; cvt.u32.u64 %0, t; }" : "=r"(a) : "l"(p));
    return a;
}
__device__ __forceinline__ void ldm_x4(uint32_t* d, uint32_t addr) {
    asm volatile("ldmatrix.sync.aligned.m8n8.x4.shared.b16 {%0,%1,%2,%3}, [%4];"
                 : "=r"(d[0]), "=r"(d[1]), "=r"(d[2]), "=r"(d[3]) : "r"(addr));
}
__device__ __forceinline__ void mma_bf16(float* c, const uint32_t* a, const uint32_t* b) {
    asm volatile(
        "mma.sync.aligned.m16n8k16.row.col.f32.bf16.bf16.f32 "
        "{%0,%1,%2,%3}, {%4,%5,%6,%7}, {%8,%9}, {%0,%1,%2,%3};"
        : "+f"(c[0]), "+f"(c[1]), "+f"(c[2]), "+f"(c[3])
        : "r"(a[0]), "r"(a[1]), "r"(a[2]), "r"(a[3]), "r"(b[0]), "r"(b[1]));
}
#define CP16(d, s, sz) asm volatile("cp.async.cg.shared.global [%0], [%1], 16, %2;" \
                                    :: "r"(d), "l"(s), "r"(sz) : "memory")
#define CP_COMMIT() asm volatile("cp.async.commit_group;" ::: "memory")
#define CP_WAIT0()  asm volatile("cp.async.wait_group 0;" ::: "memory")

__device__ __forceinline__ uint32_t pack_hi(float a, float b) {
    __nv_bfloat16 ha = __float2bfloat16(a), hb = __float2bfloat16(b);
    return (uint32_t)__bfloat16_as_ushort(ha) | ((uint32_t)__bfloat16_as_ushort(hb) << 16);
}
__device__ __forceinline__ uint32_t pack_lo(float a, float b) {
    __nv_bfloat16 ha = __float2bfloat16(a), hb = __float2bfloat16(b);
    float ra = a - __bfloat162float(ha), rb = b - __bfloat162float(hb);
    __nv_bfloat16 la = __float2bfloat16(ra), lb = __float2bfloat16(rb);
    return (uint32_t)__bfloat16_as_ushort(la) | ((uint32_t)__bfloat16_as_ushort(lb) << 16);
}

// ============================ init ============================
__global__ void init_kernel() {
    int i = blockIdx.x * blockDim.x + threadIdx.x;
    if (i < NN) g_counts[i] = 0;
    if (i < HH) g_hsum[i] = 0.f;
}

// ============================ weight prep ============================
__device__ __forceinline__ void split_store(float v, __nv_bfloat16* ph, __nv_bfloat16* pl, int idx) {
    __nv_bfloat16 h = __float2bfloat16(v);
    ph[idx] = h;
    pl[idx] = __float2bfloat16(v - __bfloat162float(h));
}
__global__ void prep_w_kernel(const float* __restrict__ W_enc,
                              const float* __restrict__ W_M,
                              const float* __restrict__ W_U) {
    int i = blockIdx.x * blockDim.x + threadIdx.x;
    if (i < 16384) {
        int n = i >> 7, k = i & 127;
        split_store(W_enc[(1 + k) * 128 + n], g_Wenc_h, g_Wenc_l, n * 128 + k);
    } else if (i < 49152) {
        int j = i - 16384;
        int n = j >> 7, k = j & 127;
        float v = (n < 128) ? W_M[k * 128 + n] : W_M[(128 + k) * 128 + (n - 128)];
        split_store(v, g_Wmsg_h, g_Wmsg_l, n * 128 + k);
    } else if (i < 81920) {
        int j = i - 49152;
        int n = j >> 8, k = j & 255;
        split_store(W_U[k * 128 + n], g_Wupd_h, g_Wupd_l, n * 256 + k);
    }
}

// ============================ activation pre-split ============================
__global__ void prep_x_kernel(const float* __restrict__ X,
                              __nv_bfloat16* __restrict__ Xh,
                              __nv_bfloat16* __restrict__ Xl, int npairs) {
    int i = blockIdx.x * blockDim.x + threadIdx.x;
    if (i < npairs) {
        float2 v = ((const float2*)X)[i];
        ((uint32_t*)Xh)[i] = pack_hi(v.x, v.y);
        ((uint32_t*)Xl)[i] = pack_lo(v.x, v.y);
    }
}

// ============================ mma.sync bf16 split GEMM ============================
#define SM_XH 0
#define SM_XL 32768
#define SM_WH 65536
#define SM_WL 81920
#define SM_TOTAL 98304

__global__ __launch_bounds__(256, 2)
void gemm_mma(const __nv_bfloat16* __restrict__ X0h, const __nv_bfloat16* __restrict__ X0l,
              const __nv_bfloat16* __restrict__ X1h, const __nv_bfloat16* __restrict__ X1l,
              int K,
              const __nv_bfloat16* __restrict__ Wh, const __nv_bfloat16* __restrict__ Wl,
              const float* __restrict__ bias0, const float* __restrict__ bias1,
              const float* __restrict__ xcol, const float* __restrict__ w0,
              float* __restrict__ C0, float* __restrict__ C1,
              __nv_bfloat16* __restrict__ Sh, __nv_bfloat16* __restrict__ Sl,
              int M, int doRelu)
{
    extern __shared__ char smem[];
    const uint32_t sb = smem_u32(smem);
    const int tid  = threadIdx.x;
    const int warp = tid >> 5;
    const int lane = tid & 31;
    const int warp_m = warp >> 1;
    const int warp_n = warp & 1;
    const int row0 = blockIdx.x * 128;
    const int nb   = blockIdx.y;
    const int halfIdx = nb >> 1;
    const int colbase = (nb & 1) * 64;

    float acc[2][4][4];
#pragma unroll
    for (int mt = 0; mt < 2; mt++)
#pragma unroll
        for (int nt = 0; nt < 4; nt++)
#pragma unroll
            for (int j = 0; j < 4; j++) acc[mt][nt][j] = 0.f;

    const int nchunks = K >> 7;
    const int a_r = lane & 15;
    const int a_k1 = (lane & 16) ? 1 : 0;
    const int b_n = (lane & 7) + ((lane & 16) ? 8 : 0);
    const int b_k1 = (lane & 8) ? 1 : 0;

    for (int c = 0; c < nchunks; c++) {
        const __nv_bfloat16* Xh = c ? X1h : X0h;
        const __nv_bfloat16* Xl = c ? X1l : X0l;
        for (int idx = tid; idx < 2048; idx += 256) {
            int row = idx >> 4, c16 = idx & 15;
            int grow = row0 + row;
            int grc = (grow < M) ? grow : 0;
            uint32_t sz = (grow < M) ? 16u : 0u;
            uint32_t soff = (uint32_t)row * 256 + (uint32_t)((c16 ^ (row & 7)) << 4);
            size_t go = (size_t)grc * 128 + (size_t)c16 * 8;
            CP16(sb + SM_XH + soff, Xh + go, sz);
            CP16(sb + SM_XL + soff, Xl + go, sz);
        }
        for (int idx = tid; idx < 1024; idx += 256) {
            int n = idx >> 4, c16 = idx & 15;
            int gn = nb * 64 + n;
            uint32_t soff = (uint32_t)n * 256 + (uint32_t)((c16 ^ (n & 7)) << 4);
            size_t go = (size_t)gn * K + (size_t)(c << 7) + (size_t)c16 * 8;
            CP16(sb + SM_WH + soff, Wh + go, 16u);
            CP16(sb + SM_WL + soff, Wl + go, 16u);
        }
        CP_COMMIT();
        CP_WAIT0();
        __syncthreads();

#pragma unroll 2
        for (int ks = 0; ks < 8; ks++) {
            const int akc = ks * 2 + a_k1;
            const int bkc = ks * 2 + b_k1;
            uint32_t ah[2][4], al[2][4];
#pragma unroll
            for (int mt = 0; mt < 2; mt++) {
                int r = warp_m * 32 + mt * 16 + a_r;
                uint32_t addr = sb + SM_XH + (uint32_t)r * 256 + (uint32_t)((akc ^ (r & 7)) << 4);
                ldm_x4(ah[mt], addr);
                ldm_x4(al[mt], addr + (SM_XL - SM_XH));
            }
            uint32_t bh[4][2], bl[4][2];
#pragma unroll
            for (int g = 0; g < 2; g++) {
                int n = warp_n * 32 + g * 16 + b_n;
                uint32_t addr = sb + SM_WH + (uint32_t)n * 256 + (uint32_t)((bkc ^ (n & 7)) << 4);
                uint32_t t[4];
                ldm_x4(t, addr);
                bh[2*g][0] = t[0];   bh[2*g][1] = t[1];
                bh[2*g+1][0] = t[2]; bh[2*g+1][1] = t[3];
                ldm_x4(t, addr + (SM_WL - SM_WH));
                bl[2*g][0] = t[0];   bl[2*g][1] = t[1];
                bl[2*g+1][0] = t[2]; bl[2*g+1][1] = t[3];
            }
#pragma unroll
            for (int mt = 0; mt < 2; mt++)
#pragma unroll
                for (int nt = 0; nt < 4; nt++) {
                    mma_bf16(acc[mt][nt], ah[mt], bh[nt]);
                    mma_bf16(acc[mt][nt], ah[mt], bl[nt]);
                    mma_bf16(acc[mt][nt], al[mt], bh[nt]);
                }
        }
        __syncthreads();
    }

    const float* bp = halfIdx ? bias1 : bias0;
    float*       Cp = halfIdx ? C1 : C0;
#pragma unroll
    for (int mt = 0; mt < 2; mt++) {
#pragma unroll
        for (int nt = 0; nt < 4; nt++) {
            int r   = row0 + warp_m * 32 + mt * 16 + (lane >> 2);
            int col = colbase + warp_n * 32 + nt * 8 + (lane & 3) * 2;
            float b0 = 0.f, b1 = 0.f, w00 = 0.f, w01 = 0.f;
            if (bp) { b0 = bp[col]; b1 = bp[col + 1]; }
            if (w0) { w00 = w0[col]; w01 = w0[col + 1]; }
#pragma unroll
            for (int half = 0; half < 2; half++) {
                int rr = r + half * 8;
                if (rr < M) {
                    float xv = xcol ? xcol[rr] : 0.f;
                    float o0 = fmaf(xv, w00, acc[mt][nt][half * 2 + 0] + b0);
                    float o1 = fmaf(xv, w01, acc[mt][nt][half * 2 + 1] + b1);
                    if (doRelu) { o0 = fmaxf(o0, 0.f); o1 = fmaxf(o1, 0.f); }
                    *(float2*)(Cp + (size_t)rr * 128 + col) = make_float2(o0, o1);
                    if (Sh) {
                        size_t so = (size_t)rr * 128 + col;
                        *(uint32_t*)(Sh + so) = pack_hi(o0, o1);
                        *(uint32_t*)(Sl + so) = pack_lo(o0, o1);
                    }
                }
            }
        }
    }
}

// ============================ CSR build ============================
__global__ void hist_kernel(const int* __restrict__ dst) {
    int e = blockIdx.x * blockDim.x + threadIdx.x;
    if (e < EE) atomicAdd(&g_counts[dst[e]], 1);
}

__global__ void scan_kernel() {
    __shared__ int part[1024];
    int t = threadIdx.x;
    const int CH = (NN + 1023) / 1024;
    int base = t * CH;
    int s = 0;
    for (int i = 0; i < CH; i++) { int idx = base + i; if (idx < NN) s += g_counts[idx]; }
    part[t] = s; __syncthreads();
    for (int off = 1; off < 1024; off <<= 1) {
        int v = (t >= off) ? part[t - off] : 0;
        __syncthreads();
        part[t] += v;
        __syncthreads();
    }
    int run = (t == 0) ? 0 : part[t - 1];
    for (int i = 0; i < CH; i++) {
        int idx = base + i;
        if (idx < NN) { g_offsets[idx] = run; g_cursor[idx] = run; run += g_counts[idx]; }
    }
    if (t == 0) g_offsets[NN] = part[1023];
}

__global__ void scatter_kernel(const int* __restrict__ src, const int* __restrict__ dst,
                               const float* __restrict__ attr) {
    int e = blockIdx.x * blockDim.x + threadIdx.x;
    if (e < EE) {
        int d = dst[e];
        int pos = atomicAdd(&g_cursor[d], 1);
        g_sedge[pos] = make_int2(src[e], __float_as_int(attr[e]));
    }
}

// ============================ per-node edge max (writes split bf16) ============================
__global__ __launch_bounds__(256)
void agg_kernel(const float* __restrict__ W_M) {
    int node = blockIdx.x * 8 + (threadIdx.x >> 5);
    if (node >= NN) return;
    int lane = threadIdx.x & 31;
    int c = lane * 4;
    float4 w4 = *(const float4*)(W_M + 256 * HH + c);
    float4 rm = make_float4(-1e30f, -1e30f, -1e30f, -1e30f);
    int e0 = g_offsets[node], e1 = g_offsets[node + 1];
    for (int e = e0; e < e1; e++) {
        int2 p = g_sedge[e];
        int s = p.x;
        float a = __int_as_float(p.y);
        float4 b4 = *(const float4*)(g_Bmat + (size_t)s * HH + c);
        rm.x = fmaxf(rm.x, fmaf(a, w4.x, b4.x));
        rm.y = fmaxf(rm.y, fmaf(a, w4.y, b4.y));
        rm.z = fmaxf(rm.z, fmaf(a, w4.z, b4.z));
        rm.w = fmaxf(rm.w, fmaf(a, w4.w, b4.w));
    }
    float4 a4 = *(const float4*)(g_Amat + (size_t)node * HH + c);
    float4 o;
    o.x = fmaxf(a4.x + rm.x, 0.f);
    o.y = fmaxf(a4.y + rm.y, 0.f);
    o.z = fmaxf(a4.z + rm.z, 0.f);
    o.w = fmaxf(a4.w + rm.w, 0.f);
    size_t so = (size_t)node * HH + c;
    *(uint32_t*)(g_ag_h + so)     = pack_hi(o.x, o.y);
    *(uint32_t*)(g_ag_h + so + 2) = pack_hi(o.z, o.w);
    *(uint32_t*)(g_ag_l + so)     = pack_lo(o.x, o.y);
    *(uint32_t*)(g_ag_l + so + 2) = pack_lo(o.z, o.w);
}

// ============================ fused decoder y + h column sums ============================
__global__ __launch_bounds__(256)
void yh_kernel(const float* __restrict__ h, const float* __restrict__ W_dec,
               const float* __restrict__ b_dec, float* __restrict__ y) {
    int warp = threadIdx.x >> 5;
    int lane = threadIdx.x & 31;
    int c = lane * 4;
    float4 wz = *(const float4*)(W_dec + c);
    float4 wh = *(const float4*)(W_dec + HH + c);
    float bd = b_dec[0];
    float4 cs = make_float4(0.f, 0.f, 0.f, 0.f);
    for (int node = blockIdx.x * 8 + warp; node < NN; node += gridDim.x * 8) {
        float4 z4 = *(const float4*)(g_z + (size_t)node * HH + c);
        float4 h4 = *(const float4*)(h + (size_t)node * HH + c);
        cs.x += h4.x; cs.y += h4.y; cs.z += h4.z; cs.w += h4.w;
        float s = z4.x * wz.x + z4.y * wz.y + z4.z * wz.z + z4.w * wz.w
                + h4.x * wh.x + h4.y * wh.y + h4.z * wh.z + h4.w * wh.w;
#pragma unroll
        for (int o = 16; o; o >>= 1) s += __shfl_down_sync(0xFFFFFFFFu, s, o);
        if (lane == 0) y[node] = s + bd;
    }
    __shared__ float sm[8][128];
    *(float4*)&sm[warp][c] = cs;
    __syncthreads();
    if (threadIdx.x < 128) {
        int col = threadIdx.x;
        float s = 0.f;
#pragma unroll
        for (int w = 0; w < 8; w++) s += sm[w][col];
        atomicAdd(&g_hsum[col], s);
    }
}

__global__ void tau_kernel(const float* __restrict__ W_term, const float* __restrict__ b_term,
                           float* __restrict__ tau) {
    __shared__ float sm[128];
    int t = threadIdx.x;
    float v = g_hsum[t] * (1.0f / (float)NN) * (W_term[t] + W_term[t + HH]);
    sm[t] = v; __syncthreads();
    for (int o = 64; o; o >>= 1) { if (t < o) sm[t] += sm[t + o]; __syncthreads(); }
    if (t == 0) tau[0] = sm[0] + b_term[0];
}

// ============================ launch ============================
extern "C" void kernel_launch(void* const* d_in, const int* in_sizes, int n_in,
                              void* d_out, int out_size)
{
    const float* x         = (const float*)d_in[0];
    const float* pre_h     = (const float*)d_in[1];
    const int*   edge_idx  = (const int*)  d_in[2];
    const float* edge_attr = (const float*)d_in[3];
    const float* W_enc     = (const float*)d_in[4];
    const float* b_enc     = (const float*)d_in[5];
    const float* W_M       = (const float*)d_in[6];
    const float* b_M       = (const float*)d_in[7];
    const float* W_U       = (const float*)d_in[8];
    const float* b_U       = (const float*)d_in[9];
    const float* W_dec     = (const float*)d_in[10];
    const float* b_dec     = (const float*)d_in[11];
    const float* W_term    = (const float*)d_in[12];
    const float* b_term    = (const float*)d_in[13];

    float* out   = (float*)d_out;
    float* h_out = out;
    float* y_out = out + (size_t)NN * HH;
    float* tau_o = out + (size_t)NN * HH + NN;

    const int* src = edge_idx;
    const int* dst = edge_idx + EE;

    float* z_p;  cudaGetSymbolAddress((void**)&z_p,  g_z);
    float* A_p;  cudaGetSymbolAddress((void**)&A_p,  g_Amat);
    float* B_p;  cudaGetSymbolAddress((void**)&B_p,  g_Bmat);
    __nv_bfloat16 *phh, *phl, *zh, *zl, *agh, *agl;
    cudaGetSymbolAddress((void**)&phh, g_ph_h);
    cudaGetSymbolAddress((void**)&phl, g_ph_l);
    cudaGetSymbolAddress((void**)&zh,  g_z_h);
    cudaGetSymbolAddress((void**)&zl,  g_z_l);
    cudaGetSymbolAddress((void**)&agh, g_ag_h);
    cudaGetSymbolAddress((void**)&agl, g_ag_l);
    __nv_bfloat16 *wench, *wencl, *wmsgh, *wmsgl, *wupdh, *wupdl;
    cudaGetSymbolAddress((void**)&wench, g_Wenc_h);
    cudaGetSymbolAddress((void**)&wencl, g_Wenc_l);
    cudaGetSymbolAddress((void**)&wmsgh, g_Wmsg_h);
    cudaGetSymbolAddress((void**)&wmsgl, g_Wmsg_l);
    cudaGetSymbolAddress((void**)&wupdh, g_Wupd_h);
    cudaGetSymbolAddress((void**)&wupdl, g_Wupd_l);

    cudaFuncSetAttribute(gemm_mma, cudaFuncAttributeMaxDynamicSharedMemorySize, SM_TOTAL);

    // fork resources (host-side only; kernel_launch runs exactly twice)
    cudaStream_t s1;
    cudaStreamCreateWithFlags(&s1, cudaStreamNonBlocking);
    cudaEvent_t evA, evB;
    cudaEventCreateWithFlags(&evA, cudaEventDisableTiming);
    cudaEventCreateWithFlags(&evB, cudaEventDisableTiming);

    const int gemmGridX   = (NN + 127) / 128;   // 391
    const int eBlocks     = (EE + 255) / 256;
    const int nWarpBlocks = (NN + 7) / 8;

    // 0) init (zeroes g_counts for hist and g_hsum for yh)
    init_kernel<<<(NN + 255) / 256, 256>>>();
    cudaEventRecord(evA, 0);

    // ---- branch s1: CSR build (independent of GEMM chain) ----
    cudaStreamWaitEvent(s1, evA, 0);
    hist_kernel<<<eBlocks, 256, 0, s1>>>(dst);
    scan_kernel<<<1, 1024, 0, s1>>>();
    scatter_kernel<<<eBlocks, 256, 0, s1>>>(src, dst, edge_attr);
    cudaEventRecord(evB, s1);

    // ---- main chain: prep + encoder + message GEMMs ----
    prep_w_kernel<<<320, 256>>>(W_enc, W_M, W_U);
    prep_x_kernel<<<(NN * 64 + 255) / 256, 256>>>(pre_h, phh, phl, NN * 64);

    gemm_mma<<<dim3(gemmGridX, 2), 256, SM_TOTAL>>>(
        phh, phl, nullptr, nullptr, 128, wench, wencl,
        b_enc, nullptr, x, W_enc, z_p, nullptr, zh, zl, NN, 1);

    gemm_mma<<<dim3(gemmGridX, 4), 256, SM_TOTAL>>>(
        zh, zl, nullptr, nullptr, 128, wmsgh, wmsgl,
        b_M, nullptr, nullptr, nullptr, A_p, B_p, nullptr, nullptr, NN, 0);

    // ---- join: agg needs both CSR and msg GEMM ----
    cudaStreamWaitEvent(0, evB, 0);
    agg_kernel<<<nWarpBlocks, 256>>>(W_M);

    // update: h = relu([z, agg] @ W_U + b_U)
    gemm_mma<<<dim3(gemmGridX, 2), 256, SM_TOTAL>>>(
        zh, zl, agh, agl, 256, wupdh, wupdl,
        b_U, nullptr, nullptr, nullptr, h_out, nullptr, nullptr, nullptr, NN, 1);

    // fused decoder + h column sums, then tau
    yh_kernel<<<384, 256>>>(h_out, W_dec, b_dec, y_out);
    tau_kernel<<<1, 128>>>(W_term, b_term, tau_o);
}